// round 4
// baseline (speedup 1.0000x reference)
#include <cuda_runtime.h>

#define NTHREADS 256
#define TB 8              // tokens per batch (kernel 1)
#define EDIM 1024
#define NQ 8
#define N_TOKENS_MAX 32768

// z scratch: 32768 tokens x 8 qubits (prefix-product expectations)
__device__ float g_z[N_TOKENS_MAX * NQ];

// ---------------------------------------------------------------------------
// Kernel 1: ang = x @ W_in^T + b_in ; m_q = cos(theta_q)*cos(ang_q) ;
//           z_q = prod_{j<=q} m_j   -> g_z
// ---------------------------------------------------------------------------
// smem: psumA[TB][1024] (q0..3 partials, float4/thread), psumB same for q4..7,
//       cth[8], bi[8]  -> 65,600 B  (3 CTAs/SM = 197 KB)
#define K1_SMEM_FLOATS (2*TB*1024 + 16)

__global__ __launch_bounds__(NTHREADS, 3)
void qff_phase1(const float* __restrict__ x,
                const float* __restrict__ W_in,
                const float* __restrict__ b_in,
                const float* __restrict__ theta,
                int n_tokens)
{
    extern __shared__ float sm[];
    float* psumA = sm;                  // TB*1024
    float* psumB = sm + TB*1024;        // TB*1024
    float* cth   = sm + 2*TB*1024;      // 8
    float* bi    = cth + 8;             // 8

    const int tid  = threadIdx.x;
    const int lane = tid & 31;
    const int wrp  = tid >> 5;

    if (tid < NQ) { cth[tid] = cosf(theta[tid]); bi[tid] = b_in[tid]; }

    // W_in register-resident (persistent block)
    float win[NQ][4];
#pragma unroll
    for (int q = 0; q < NQ; q++) {
        float4 w = reinterpret_cast<const float4*>(W_in + q*EDIM)[tid];
        win[q][0]=w.x; win[q][1]=w.y; win[q][2]=w.z; win[q][3]=w.w;
    }
    __syncthreads();

    const int q2 = lane >> 2;           // qubit for stage 2
    const int c2 = lane & 3;            // chunk (64 partials each)
    const int hb = q2 >> 2;             // 0: psumA, 1: psumB
    const int qm = q2 & 3;
    const unsigned ex = ((unsigned)(2*c2 + hb)) << 4;  // XOR bank stagger (bytes)

    const int nbatches = n_tokens / TB;
    const float4* x4 = reinterpret_cast<const float4*>(x);

    // prologue: load first batch
    int batch = blockIdx.x;
    float4 xv[TB];
    {
        const float4* r = x4 + (long)batch * TB * (EDIM/4) + tid;
#pragma unroll
        for (int t = 0; t < TB; t++) xv[t] = r[t*(EDIM/4)];
    }

    for (; batch < nbatches; batch += gridDim.x) {
        // ---- phase 1: per-thread 4-col partial dots, 2x STS.128 per token ----
#pragma unroll
        for (int t = 0; t < TB; t++) {
            float p[NQ];
#pragma unroll
            for (int q = 0; q < NQ; q++) {
                float a = xv[t].x * win[q][0];
                a = fmaf(xv[t].y, win[q][1], a);
                a = fmaf(xv[t].z, win[q][2], a);
                a = fmaf(xv[t].w, win[q][3], a);
                p[q] = a;
            }
            reinterpret_cast<float4*>(psumA + t*EDIM)[tid] = make_float4(p[0],p[1],p[2],p[3]);
            reinterpret_cast<float4*>(psumB + t*EDIM)[tid] = make_float4(p[4],p[5],p[6],p[7]);
        }

        // ---- software pipeline: prefetch next batch's x (xv now dead) ----
        {
            int nb = batch + gridDim.x;
            long pb = (long)((nb < nbatches) ? nb : batch) * TB * (EDIM/4);
            const float4* r = x4 + pb + tid;
#pragma unroll
            for (int t = 0; t < TB; t++) xv[t] = r[t*(EDIM/4)];
        }
        __syncthreads();

        // ---- stage 2: warp `wrp` reduces token wrp; XOR-staggered banks ----
        {
            // partial i = c2*64 + (j^e) for qubit q2 of token wrp lives at
            // byte offset i*16 + qm*4 in (hb? psumB : psumA) + wrp*EDIM
            const float* arr = (hb ? psumB : psumA) + wrp*EDIM;
            const char* pbase = reinterpret_cast<const char*>(arr + qm)
                              + (unsigned)c2 * 1024u;     // chunk base (bank-neutral)
            float s0=0.f, s1=0.f, s2=0.f, s3=0.f;
#pragma unroll
            for (int j = 0; j < 64; j += 4) {
                s0 += *reinterpret_cast<const float*>(pbase + (((unsigned)(j+0)<<4) ^ ex));
                s1 += *reinterpret_cast<const float*>(pbase + (((unsigned)(j+1)<<4) ^ ex));
                s2 += *reinterpret_cast<const float*>(pbase + (((unsigned)(j+2)<<4) ^ ex));
                s3 += *reinterpret_cast<const float*>(pbase + (((unsigned)(j+3)<<4) ^ ex));
            }
            float s = (s0+s1) + (s2+s3);
            s += __shfl_down_sync(0xffffffffu, s, 1);
            s += __shfl_down_sync(0xffffffffu, s, 2);   // c2==0 lanes: full dot
            float m = cth[q2] * cosf(s + bi[q2]);       // cos(theta_q)*cos(ang_q)
            float zv = m;                                // prefix product over q
#pragma unroll
            for (int off = 4; off <= 16; off <<= 1) {
                float pp = __shfl_up_sync(0xffffffffu, zv, off);
                if (lane >= off) zv *= pp;               // sources are c2==0 lanes
            }
            if (c2 == 0) {
                long tok = (long)batch * TB + wrp;
                g_z[tok*NQ + q2] = zv;
            }
        }
        __syncthreads();   // psum reuse guard for next batch
    }
}

// ---------------------------------------------------------------------------
// Kernel 2: out = relu(z @ W_out^T + b_out)  — streaming expand
// ---------------------------------------------------------------------------
__global__ __launch_bounds__(NTHREADS, 4)
void qff_phase2(const float* __restrict__ W_out,
                const float* __restrict__ b_out,
                float* __restrict__ out,
                int n_tokens)
{
    const int tid = threadIdx.x;

    // W_out rows for e = 4*tid .. 4*tid+3, register-resident
    float4 wA[4], wB[4];
#pragma unroll
    for (int j = 0; j < 4; j++) {
        wA[j] = reinterpret_cast<const float4*>(W_out)[(4*tid+j)*2 + 0];
        wB[j] = reinterpret_cast<const float4*>(W_out)[(4*tid+j)*2 + 1];
    }
    const float4 bo = reinterpret_cast<const float4*>(b_out)[tid];

    const float4* z4 = reinterpret_cast<const float4*>(g_z);
    float4* out4 = reinterpret_cast<float4*>(out);

    int tok = blockIdx.x;
    if (tok >= n_tokens) return;

    // double-buffered z (32B broadcast per token)
    float4 zlo = z4[tok*2 + 0];
    float4 zhi = z4[tok*2 + 1];

    while (tok < n_tokens) {
        int nt = tok + gridDim.x;
        int pt = (nt < n_tokens) ? nt : tok;
        float4 zlc = zlo, zhc = zhi;
        zlo = z4[pt*2 + 0];            // prefetch next token's z
        zhi = z4[pt*2 + 1];

        float4 r;
        {
            float a0 = bo.x, a1 = bo.y, a2 = bo.z, a3 = bo.w;
            a0 = fmaf(zlc.x, wA[0].x, a0); a1 = fmaf(zlc.x, wA[1].x, a1);
            a2 = fmaf(zlc.x, wA[2].x, a2); a3 = fmaf(zlc.x, wA[3].x, a3);
            a0 = fmaf(zlc.y, wA[0].y, a0); a1 = fmaf(zlc.y, wA[1].y, a1);
            a2 = fmaf(zlc.y, wA[2].y, a2); a3 = fmaf(zlc.y, wA[3].y, a3);
            a0 = fmaf(zlc.z, wA[0].z, a0); a1 = fmaf(zlc.z, wA[1].z, a1);
            a2 = fmaf(zlc.z, wA[2].z, a2); a3 = fmaf(zlc.z, wA[3].z, a3);
            a0 = fmaf(zlc.w, wA[0].w, a0); a1 = fmaf(zlc.w, wA[1].w, a1);
            a2 = fmaf(zlc.w, wA[2].w, a2); a3 = fmaf(zlc.w, wA[3].w, a3);
            a0 = fmaf(zhc.x, wB[0].x, a0); a1 = fmaf(zhc.x, wB[1].x, a1);
            a2 = fmaf(zhc.x, wB[2].x, a2); a3 = fmaf(zhc.x, wB[3].x, a3);
            a0 = fmaf(zhc.y, wB[0].y, a0); a1 = fmaf(zhc.y, wB[1].y, a1);
            a2 = fmaf(zhc.y, wB[2].y, a2); a3 = fmaf(zhc.y, wB[3].y, a3);
            a0 = fmaf(zhc.z, wB[0].z, a0); a1 = fmaf(zhc.z, wB[1].z, a1);
            a2 = fmaf(zhc.z, wB[2].z, a2); a3 = fmaf(zhc.z, wB[3].z, a3);
            a0 = fmaf(zhc.w, wB[0].w, a0); a1 = fmaf(zhc.w, wB[1].w, a1);
            a2 = fmaf(zhc.w, wB[2].w, a2); a3 = fmaf(zhc.w, wB[3].w, a3);
            r = make_float4(fmaxf(a0,0.f), fmaxf(a1,0.f), fmaxf(a2,0.f), fmaxf(a3,0.f));
        }
        out4[(long)tok * (EDIM/4) + tid] = r;
        tok = nt;
    }
}

extern "C" void kernel_launch(void* const* d_in, const int* in_sizes, int n_in,
                              void* d_out, int out_size) {
    const float* x     = (const float*)d_in[0];
    const float* W_in  = (const float*)d_in[1];
    const float* b_in  = (const float*)d_in[2];
    const float* theta = (const float*)d_in[3];
    const float* W_out = (const float*)d_in[4];
    const float* b_out = (const float*)d_in[5];
    float* out = (float*)d_out;

    const int n_tokens = in_sizes[0] / EDIM;   // 32768

    const size_t smem1 = K1_SMEM_FLOATS * sizeof(float);   // 65,600 B
    cudaFuncSetAttribute(qff_phase1, cudaFuncAttributeMaxDynamicSharedMemorySize, (int)smem1);

    qff_phase1<<<444, NTHREADS, smem1>>>(x, W_in, b_in, theta, n_tokens);
    qff_phase2<<<592, NTHREADS>>>(W_out, b_out, out, n_tokens);
}

// round 5
// speedup vs baseline: 1.5397x; 1.5397x over previous
#include <cuda_runtime.h>

#define NTHREADS 256
#define TB 8              // tokens per batch
#define EDIM 1024
#define NQ 8

typedef unsigned long long u64;

__device__ __forceinline__ u64 pack2(float lo, float hi) {
    u64 r; asm("mov.b64 %0, {%1, %2};" : "=l"(r) : "f"(lo), "f"(hi)); return r;
}
__device__ __forceinline__ u64 packdup(float v) {
    u64 r; asm("mov.b64 %0, {%1, %1};" : "=l"(r) : "f"(v)); return r;
}
__device__ __forceinline__ void unpack2(u64 p, float& lo, float& hi) {
    asm("mov.b64 {%0, %1}, %2;" : "=f"(lo), "=f"(hi) : "l"(p));
}
__device__ __forceinline__ u64 mul2(u64 a, u64 b) {
    u64 r; asm("mul.rn.f32x2 %0, %1, %2;" : "=l"(r) : "l"(a), "l"(b)); return r;
}
__device__ __forceinline__ u64 fma2(u64 a, u64 b, u64 c) {
    u64 r; asm("fma.rn.f32x2 %0, %1, %2, %3;" : "=l"(r) : "l"(a), "l"(b), "l"(c)); return r;
}
__device__ __forceinline__ u64 add2(u64 a, u64 b) {
    u64 r; asm("add.rn.f32x2 %0, %1, %2;" : "=l"(r) : "l"(a), "l"(b)); return r;
}

// smem: psum pair-arrays 4 x (TB*256 float2) = 64KB, zdup TB*16, cth 8, bi 8
#define PSUM_F   (4*TB*512)
#define SMEM_FLOATS (PSUM_F + TB*16 + 16)

__global__ __launch_bounds__(NTHREADS, 2)
void qff_fused(const float* __restrict__ x,
               const float* __restrict__ W_in,
               const float* __restrict__ b_in,
               const float* __restrict__ theta,
               const float* __restrict__ W_out,
               const float* __restrict__ b_out,
               float* __restrict__ out,
               int n_tokens)
{
    extern __shared__ float sm[];
    float* psum = sm;                 // 4 pair-arrays, each TB*512 floats
    float* zdup = sm + PSUM_F;        // TB*16 floats: [z0,z0,z1,z1,...]
    float* cth  = zdup + TB*16;       // 8
    float* bi   = cth + 8;            // 8

    const int tid  = threadIdx.x;
    const int lane = tid & 31;
    const int wrp  = tid >> 5;

    if (tid < NQ) { cth[tid] = cosf(theta[tid]); bi[tid] = b_in[tid]; }

    // ---- W_in pairs: wi[pr][c] = (W_in[2pr][4t+c], W_in[2pr+1][4t+c]) ----
    u64 wi[4][4];
#pragma unroll
    for (int pr = 0; pr < 4; pr++) {
        float4 wa = reinterpret_cast<const float4*>(W_in + (2*pr  )*EDIM)[tid];
        float4 wb = reinterpret_cast<const float4*>(W_in + (2*pr+1)*EDIM)[tid];
        wi[pr][0] = pack2(wa.x, wb.x);
        wi[pr][1] = pack2(wa.y, wb.y);
        wi[pr][2] = pack2(wa.z, wb.z);
        wi[pr][3] = pack2(wa.w, wb.w);
    }
    // ---- W_out pairs: wo01[k]=(W[e0][k],W[e1][k]), wo23[k]=(W[e2][k],W[e3][k]) ----
    u64 wo01[8], wo23[8];
    {
        float4 rA[4], rB[4];
#pragma unroll
        for (int j = 0; j < 4; j++) {
            rA[j] = reinterpret_cast<const float4*>(W_out)[(4*tid+j)*2 + 0];  // k0..3
            rB[j] = reinterpret_cast<const float4*>(W_out)[(4*tid+j)*2 + 1];  // k4..7
        }
        wo01[0]=pack2(rA[0].x,rA[1].x); wo01[1]=pack2(rA[0].y,rA[1].y);
        wo01[2]=pack2(rA[0].z,rA[1].z); wo01[3]=pack2(rA[0].w,rA[1].w);
        wo01[4]=pack2(rB[0].x,rB[1].x); wo01[5]=pack2(rB[0].y,rB[1].y);
        wo01[6]=pack2(rB[0].z,rB[1].z); wo01[7]=pack2(rB[0].w,rB[1].w);
        wo23[0]=pack2(rA[2].x,rA[3].x); wo23[1]=pack2(rA[2].y,rA[3].y);
        wo23[2]=pack2(rA[2].z,rA[3].z); wo23[3]=pack2(rA[2].w,rA[3].w);
        wo23[4]=pack2(rB[2].x,rB[3].x); wo23[5]=pack2(rB[2].y,rB[3].y);
        wo23[6]=pack2(rB[2].z,rB[3].z); wo23[7]=pack2(rB[2].w,rB[3].w);
    }
    u64 bo01, bo23;
    { float4 bo = reinterpret_cast<const float4*>(b_out)[tid];
      bo01 = pack2(bo.x, bo.y); bo23 = pack2(bo.z, bo.w); }

    __syncthreads();

    // stage-2 lane constants: pair pr2 = lane>>3, chunk c8 = lane&7
    const int pr2 = lane >> 3;
    const int c8  = lane & 7;
    const unsigned ex = ((unsigned)(2*c8 + (pr2 & 1))) << 3;   // byte XOR stagger

    const int nbatches = n_tokens / TB;
    const float4* x4 = reinterpret_cast<const float4*>(x);
    float4* out4 = reinterpret_cast<float4*>(out);

    // prologue: load first batch
    int batch = blockIdx.x;
    float4 xv[TB];
    {
        const float4* r = x4 + (long)batch * TB * (EDIM/4) + tid;
#pragma unroll
        for (int t = 0; t < TB; t++) xv[t] = r[t*(EDIM/4)];
    }

    for (; batch < nbatches; batch += gridDim.x) {
        // ---- phase 1: packed partial dots, 4x STS.64 per token ----
#pragma unroll
        for (int t = 0; t < TB; t++) {
            u64 xx = packdup(xv[t].x), xy = packdup(xv[t].y);
            u64 xz = packdup(xv[t].z), xw = packdup(xv[t].w);
#pragma unroll
            for (int pr = 0; pr < 4; pr++) {
                u64 a = mul2(xx, wi[pr][0]);
                a = fma2(xy, wi[pr][1], a);
                a = fma2(xz, wi[pr][2], a);
                a = fma2(xw, wi[pr][3], a);
                reinterpret_cast<u64*>(psum + pr*(TB*512))[t*256 + tid] = a;
            }
        }

        // ---- prefetch next batch's x (xv dead) ----
        {
            int nb = batch + gridDim.x;
            long pb = (long)((nb < nbatches) ? nb : batch) * TB * (EDIM/4);
            const float4* r = x4 + pb + tid;
#pragma unroll
            for (int t = 0; t < TB; t++) xv[t] = r[t*(EDIM/4)];
        }
        __syncthreads();   // sync A: psum ready

        // ---- stage 2: warp wrp reduces token wrp ----
        {
            // pair i = c8*32 + (j^e); LDS.64 banks conflict-free (i mod 16 distinct/phase)
            const char* pbase = reinterpret_cast<const char*>(
                  reinterpret_cast<const u64*>(psum + pr2*(TB*512)) + wrp*256 + c8*32);
            u64 a0, a1, a2, a3;
            a0 = *reinterpret_cast<const u64*>(pbase + (0u ^ ex));
            a1 = *reinterpret_cast<const u64*>(pbase + (8u ^ ex));
            a2 = *reinterpret_cast<const u64*>(pbase + (16u ^ ex));
            a3 = *reinterpret_cast<const u64*>(pbase + (24u ^ ex));
#pragma unroll
            for (int j = 4; j < 32; j += 4) {
                a0 = add2(a0, *reinterpret_cast<const u64*>(pbase + (((unsigned)(j+0)<<3) ^ ex)));
                a1 = add2(a1, *reinterpret_cast<const u64*>(pbase + (((unsigned)(j+1)<<3) ^ ex)));
                a2 = add2(a2, *reinterpret_cast<const u64*>(pbase + (((unsigned)(j+2)<<3) ^ ex)));
                a3 = add2(a3, *reinterpret_cast<const u64*>(pbase + (((unsigned)(j+3)<<3) ^ ex)));
            }
            u64 acc = add2(add2(a0, a1), add2(a2, a3));
            float sa, sb; unpack2(acc, sa, sb);
            // reduce over the 8 chunk-lanes
            sa += __shfl_down_sync(0xffffffffu, sa, 1);
            sb += __shfl_down_sync(0xffffffffu, sb, 1);
            sa += __shfl_down_sync(0xffffffffu, sa, 2);
            sb += __shfl_down_sync(0xffffffffu, sb, 2);
            sa += __shfl_down_sync(0xffffffffu, sa, 4);
            sb += __shfl_down_sync(0xffffffffu, sb, 4);
            // m_q = cos(theta_q) * cos(ang_q)   (valid on c8==0 lanes)
            float ma = cth[2*pr2  ] * cosf(sa + bi[2*pr2  ]);
            float mb = cth[2*pr2+1] * cosf(sb + bi[2*pr2+1]);
            float pp = ma * mb;                 // pair product
            float incl = pp;                    // inclusive prefix over pairs (lanes 8*pr2)
            float tt;
            tt = __shfl_up_sync(0xffffffffu, incl, 8);  if (lane >= 8)  incl *= tt;
            tt = __shfl_up_sync(0xffffffffu, incl, 16); if (lane >= 16) incl *= tt;
            float E = __shfl_up_sync(0xffffffffu, incl, 8);             // exclusive
            if (pr2 == 0) E = 1.0f;
            float za = E * ma;                  // z_{2pr2}
            float zb = E * pp;                  // z_{2pr2+1}
            if (c8 == 0)
                reinterpret_cast<float4*>(zdup + wrp*16)[pr2] = make_float4(za, za, zb, zb);
        }
        __syncthreads();   // sync B: zdup ready, psum free

        // ---- phase 3: out = relu(z @ W_out^T + b_out) ----
        float4* orow = out4 + (long)batch * TB * (EDIM/4) + tid;
#pragma unroll
        for (int t = 0; t < TB; t++) {
            const ulonglong2* zr = reinterpret_cast<const ulonglong2*>(zdup + t*16);
            ulonglong2 z01 = zr[0];   // (z0,z0),(z1,z1)
            ulonglong2 z23 = zr[1];
            ulonglong2 z45 = zr[2];
            ulonglong2 z67 = zr[3];
            u64 acc01 = bo01, acc23 = bo23;
            acc01 = fma2(z01.x, wo01[0], acc01);  acc23 = fma2(z01.x, wo23[0], acc23);
            acc01 = fma2(z01.y, wo01[1], acc01);  acc23 = fma2(z01.y, wo23[1], acc23);
            acc01 = fma2(z23.x, wo01[2], acc01);  acc23 = fma2(z23.x, wo23[2], acc23);
            acc01 = fma2(z23.y, wo01[3], acc01);  acc23 = fma2(z23.y, wo23[3], acc23);
            acc01 = fma2(z45.x, wo01[4], acc01);  acc23 = fma2(z45.x, wo23[4], acc23);
            acc01 = fma2(z45.y, wo01[5], acc01);  acc23 = fma2(z45.y, wo23[5], acc23);
            acc01 = fma2(z67.x, wo01[6], acc01);  acc23 = fma2(z67.x, wo23[6], acc23);
            acc01 = fma2(z67.y, wo01[7], acc01);  acc23 = fma2(z67.y, wo23[7], acc23);
            float a0, a1, a2, a3;
            unpack2(acc01, a0, a1);
            unpack2(acc23, a2, a3);
            orow[t*(EDIM/4)] = make_float4(fmaxf(a0,0.f), fmaxf(a1,0.f),
                                           fmaxf(a2,0.f), fmaxf(a3,0.f));
        }
        // next-iter psum writes guarded by sync B; next zdup writes by next sync A
    }
}

extern "C" void kernel_launch(void* const* d_in, const int* in_sizes, int n_in,
                              void* d_out, int out_size) {
    const float* x     = (const float*)d_in[0];
    const float* W_in  = (const float*)d_in[1];
    const float* b_in  = (const float*)d_in[2];
    const float* theta = (const float*)d_in[3];
    const float* W_out = (const float*)d_in[4];
    const float* b_out = (const float*)d_in[5];
    float* out = (float*)d_out;

    const int n_tokens = in_sizes[0] / EDIM;   // 32768

    const size_t smem = SMEM_FLOATS * sizeof(float);   // ~66.1 KB
    cudaFuncSetAttribute(qff_fused, cudaFuncAttributeMaxDynamicSharedMemorySize, (int)smem);
    qff_fused<<<296, NTHREADS, smem>>>(x, W_in, b_in, theta, W_out, b_out, out, n_tokens);
}